// round 8
// baseline (speedup 1.0000x reference)
#include <cuda_runtime.h>
#include <cstdint>

#define B_    2
#define NH_   8
#define N_    4096
#define D_    64
#define K2_   49
#define V_F4  784          // D*K2/4
#define THREADS 128
#define ROWS  8            // rows per CTA (8 | 4096 so h constant per CTA)

__device__ __forceinline__ uint32_t smem_u32(const void* p) {
    return (uint32_t)__cvta_generic_to_shared(p);
}
__device__ __forceinline__ void cp16(uint32_t dst, const void* src) {
    // .cg: v_local is pure streaming, keep it out of L1
    asm volatile("cp.async.cg.shared.global [%0], [%1], 16;\n" :: "r"(dst), "l"(src));
}
__device__ __forceinline__ void cp4(uint32_t dst, const void* src) {
    asm volatile("cp.async.ca.shared.global [%0], [%1], 4;\n" :: "r"(dst), "l"(src));
}
__device__ __forceinline__ void cp_commit() {
    asm volatile("cp.async.commit_group;\n" ::: "memory");
}
template <int NPend>
__device__ __forceinline__ void cp_wait() {
    asm volatile("cp.async.wait_group %0;\n" :: "n"(NPend) : "memory");
}

struct __align__(16) Stage {
    float4 v[V_F4];        // 12544 B
};

__global__ __launch_bounds__(THREADS)
void sw_attention_av_fused2(const float* __restrict__ q_norm,      // [B,NH,N,D]
                            const float* __restrict__ attn_local,  // [B,NH,N,K2]
                            const float* __restrict__ v_local,     // [B,NH,N,D,K2]
                            const float* __restrict__ tokens,      // [NH,D,K2]
                            const float* __restrict__ bias,        // [NH,N,K2]
                            float* __restrict__ out)               // [B,NH,N,D]
{
    __shared__ Stage st[2];                 // 25088 B
    __shared__ float s_attn[ROWS * K2_];    // 392 floats, contiguous == global layout

    const int t    = threadIdx.x;
    const int row0 = blockIdx.x * ROWS;
    const int h    = (row0 >> 12) & (NH_ - 1);
    const int n0   = row0 & (N_ - 1);

    auto prefetch_v = [&](int s, int row) {
        const float4* vrow = reinterpret_cast<const float4*>(v_local) + (size_t)row * V_F4;
        uint32_t vdst = smem_u32(st[s].v);
#pragma unroll
        for (int i = 0; i < 6; i++)
            cp16(vdst + (uint32_t)(t + THREADS * i) * 16u, vrow + t + THREADS * i);
        if (t < V_F4 - 6 * THREADS)                 // 16 leftover float4
            cp16(vdst + (uint32_t)(t + 6 * THREADS) * 16u, vrow + t + 6 * THREADS);
        cp_commit();
    };

    // ---- group A: attn_local (8 rows, contiguous) -> s_attn
    {
        const float* al0 = attn_local + (size_t)row0 * K2_;
        uint32_t adst = smem_u32(s_attn);
#pragma unroll
        for (int i = 0; i < 3; i++)                 // 3*128 = 384
            cp4(adst + (uint32_t)(t + THREADS * i) * 4u, al0 + t + THREADS * i);
        if (t < ROWS * K2_ - 3 * THREADS)           // 8 leftover
            cp4(adst + (uint32_t)(t + 3 * THREADS) * 4u, al0 + t + 3 * THREADS);
        cp_commit();
    }
    // ---- group B: v stage 0 (committed after A, so wait<1> retires A first)
    prefetch_v(0, row0);
    cp_wait<1>();                                   // this thread's A slice landed

    // ---- gemv burst: all 8 rows' attn while v0 streams in.
    // unit u = row*49 + k; each thread owns u = t, t+128, t+256 (+t+384 if t<8)
    {
        const float* q0    = q_norm + (size_t)row0 * D_;
        const float* tok_h = tokens + h * (D_ * K2_);
        const float* b0    = bias + ((size_t)h * N_ + n0) * K2_;
        for (int u = t; u < ROWS * K2_; u += THREADS) {
            const int row = u / K2_;
            const int k   = u - row * K2_;
            const float* qp = q0 + row * D_;        // L1-hot (2 KB per CTA)
            const float* tp = tok_h + k;            // L1-hot (12.5 KB per head)
            float a0 = 0.f, a1 = 0.f;
#pragma unroll
            for (int d = 0; d < D_; d += 2) {
                a0 = fmaf(__ldg(qp + d),     __ldg(tp + d * K2_),       a0);
                a1 = fmaf(__ldg(qp + d + 1), __ldg(tp + (d + 1) * K2_), a1);
            }
            // s_attn[u] was cp'd by THIS thread (same index set) -> visible
            s_attn[u] += a0 + a1 + __ldg(b0 + u);
        }
    }
    __syncthreads();                                // attn visible to all

    // ---- pure streaming loop (identical skeleton to the 82.7%-DRAM kernel)
    for (int r = 0; r < ROWS; r++) {
        if (r + 1 < ROWS) {
            prefetch_v((r + 1) & 1, row0 + r + 1);  // other slot, freed at r-1 tail
            cp_wait<1>();                           // stage r complete
        } else {
            cp_wait<0>();
        }
        __syncthreads();                            // stage r visible to all

        const Stage& S = st[r & 1];

        if (t < D_) {
            const float* vd = reinterpret_cast<const float*>(S.v) + t * K2_;
            const float* ak = s_attn + r * K2_;
            float acc0 = 0.f, acc1 = 0.f;
#pragma unroll
            for (int k = 0; k < 48; k += 2) {
                acc0 = fmaf(ak[k + 0], vd[k + 0], acc0);
                acc1 = fmaf(ak[k + 1], vd[k + 1], acc1);
            }
            acc0 = fmaf(ak[48], vd[48], acc0);
            out[(size_t)(row0 + r) * D_ + t] = acc0 + acc1;
        }

        __syncthreads();                            // readers done before slot reuse
    }
}

extern "C" void kernel_launch(void* const* d_in, const int* in_sizes, int n_in,
                              void* d_out, int out_size)
{
    const float* q_norm     = (const float*)d_in[0];
    const float* attn_local = (const float*)d_in[1];
    const float* v_local    = (const float*)d_in[2];
    const float* tokens     = (const float*)d_in[3];
    const float* bias       = (const float*)d_in[4];
    float* out = (float*)d_out;

    const int blocks = (B_ * NH_ * N_) / ROWS;      // 8192
    sw_attention_av_fused2<<<blocks, THREADS>>>(q_norm, attn_local, v_local,
                                                tokens, bias, out);
}